// round 1
// baseline (speedup 1.0000x reference)
#include <cuda_runtime.h>
#include <cstdint>

#define NB 4
#define CC 64
#define HH 256
#define WW 256
#define SS 65536    // H*W
#define NS 262144   // NB*SS

// ---------------- scratch (device globals; no allocs allowed) ----------------
__device__ float g_xt[(size_t)NS * CC];        // x transposed to [N,H,W,C]
__device__ float g_K [(size_t)NB * CC * SS];   // keys    [N,C,S]
__device__ float g_V [(size_t)NB * CC * SS];   // values  [N,C,S]
__device__ float g_Qt[(size_t)NS * CC];        // queries [N,S,C] (pixel-major)
__device__ float g_stats[NB * CC * 2];         // per key-row: max, sumexp
__device__ float g_ctxp[16 * 64 * 256];        // context partials [nh][chunk][k*16+v]
__device__ float g_ctx [16 * 256];             // context [nh][k*16+v]
__device__ float g_B  [NB * 64 * 64];          // folded (ctx^T ∘ rp_w)/Z  [n][o][kk]

// ---------------- packed f32x2 helpers ----------------
__device__ __forceinline__ unsigned long long pk2(float lo, float hi) {
    unsigned long long r;
    asm("mov.b64 %0, {%1, %2};" : "=l"(r) : "f"(lo), "f"(hi));
    return r;
}
__device__ __forceinline__ void upk2(unsigned long long v, float& lo, float& hi) {
    asm("mov.b64 {%0, %1}, %2;" : "=f"(lo), "=f"(hi) : "l"(v));
}
__device__ __forceinline__ unsigned long long fma2(unsigned long long a,
                                                   unsigned long long b,
                                                   unsigned long long c) {
    unsigned long long d;
    asm("fma.rn.f32x2 %0, %1, %2, %3;" : "=l"(d) : "l"(a), "l"(b), "l"(c));
    return d;
}

// ---------------- K0: transpose x [N,C,S] -> g_xt [N,S,C] ----------------
__global__ __launch_bounds__(256) void k0_transpose(const float* __restrict__ x) {
    __shared__ float sh[64][65];
    long gs0 = (long)blockIdx.x * 64;         // 4096 blocks, 64 pixels each
    int n  = (int)(gs0 >> 16);
    int s0 = (int)(gs0 & 65535);
    const float* xb = x + (size_t)n * CC * SS + s0;
    for (int idx = threadIdx.x; idx < 4096; idx += 256) {
        int c = idx >> 6, p = idx & 63;
        sh[c][p] = xb[(size_t)c * SS + p];
    }
    __syncthreads();
    float* xtb = g_xt + (size_t)gs0 * 64;
    for (int idx = threadIdx.x; idx < 4096; idx += 256) {
        int p = idx >> 6, c = idx & 63;
        xtb[(size_t)p * 64 + c] = sh[c][p];
    }
}

// ---------------- K1: offsets + bilinear sample + 3 projections ----------------
// 256 threads = 32 pixels x 8 lanes (each lane owns 8 channels).
__global__ __launch_bounds__(256) void k1_kqv(
    const float* __restrict__ kow, const float* __restrict__ kob, const float* __restrict__ kw,
    const float* __restrict__ qow, const float* __restrict__ qob, const float* __restrict__ qw,
    const float* __restrict__ vow, const float* __restrict__ vob, const float* __restrict__ vw) {
    __shared__ float w_s[64][68];
    __shared__ float sm_s[32][68];
    __shared__ float sm_o[64][33];
    __shared__ float ow_s[6][64];
    __shared__ float ob_s[8];

    int tid  = threadIdx.x;
    int pixL = tid >> 3;
    int tg   = tid & 7;
    int c0   = tg * 8;

    long pg0 = (long)blockIdx.x * 32;          // 8192 blocks
    int n    = (int)(pg0 >> 16);
    int sIn  = (int)(pg0 & 65535);
    long pG  = pg0 + pixL;
    int s    = sIn + pixL;
    int yI   = s >> 8;
    int xI   = s & 255;

    // stage offset weights/biases
    for (int i = tid; i < 128; i += 256) ow_s[0 + (i >> 6)][i & 63] = kow[i];
    for (int i = tid; i < 128; i += 256) ow_s[2 + (i >> 6)][i & 63] = qow[i];
    for (int i = tid; i < 128; i += 256) ow_s[4 + (i >> 6)][i & 63] = vow[i];
    if (tid < 2) { ob_s[tid] = kob[tid]; ob_s[2 + tid] = qob[tid]; ob_s[4 + tid] = vob[tid]; }

    // center-pixel channels (for offset dot products)
    const float* xp = g_xt + (size_t)pG * 64 + c0;
    float4 xa = *(const float4*)xp;
    float4 xb4 = *(const float4*)(xp + 4);
    __syncthreads();

    float od[6];
#pragma unroll
    for (int d = 0; d < 6; d++) {
        const float* w8 = &ow_s[d][c0];
        float a = xa.x * w8[0] + xa.y * w8[1] + xa.z * w8[2] + xa.w * w8[3]
                + xb4.x * w8[4] + xb4.y * w8[5] + xb4.z * w8[6] + xb4.w * w8[7];
        a += __shfl_xor_sync(0xffffffffu, a, 1);
        a += __shfl_xor_sync(0xffffffffu, a, 2);
        a += __shfl_xor_sync(0xffffffffu, a, 4);
        od[d] = a + ob_s[d];
    }

    const float* wproj[3] = {kw, qw, vw};

    for (int pr = 0; pr < 3; pr++) {
        // stage projection weight [o][c]
        const float* wp = wproj[pr];
        for (int i = tid; i < 4096; i += 256) w_s[i >> 6][i & 63] = wp[i];

        // bilinear sample (8 channels per thread)
        float py = (float)yI + od[pr * 2 + 0];
        float px = (float)xI + od[pr * 2 + 1];
        float y0f = floorf(py), x0f = floorf(px);
        int iy0 = (int)y0f, ix0 = (int)x0f;
        float ty = py - y0f, tx = px - x0f;
        float wgt0 = (1.f - ty) * (1.f - tx);
        float wgt1 = (1.f - ty) * tx;
        float wgt2 = ty * (1.f - tx);
        float wgt3 = ty * tx;
        float acc8[8] = {0.f, 0.f, 0.f, 0.f, 0.f, 0.f, 0.f, 0.f};
        float wgt[4] = {wgt0, wgt1, wgt2, wgt3};
#pragma unroll
        for (int t = 0; t < 4; t++) {
            int iy = iy0 + (t >> 1);
            int ix = ix0 + (t & 1);
            if (iy >= 0 && iy < 256 && ix >= 0 && ix < 256) {
                const float* tp = g_xt + ((((size_t)n << 16) | ((size_t)iy << 8) | (size_t)ix) * 64) + c0;
                float4 a = *(const float4*)tp;
                float4 b = *(const float4*)(tp + 4);
                float w = wgt[t];
                acc8[0] += w * a.x; acc8[1] += w * a.y; acc8[2] += w * a.z; acc8[3] += w * a.w;
                acc8[4] += w * b.x; acc8[5] += w * b.y; acc8[6] += w * b.z; acc8[7] += w * b.w;
            }
        }
        *(float4*)&sm_s[pixL][c0]     = make_float4(acc8[0], acc8[1], acc8[2], acc8[3]);
        *(float4*)&sm_s[pixL][c0 + 4] = make_float4(acc8[4], acc8[5], acc8[6], acc8[7]);
        __syncthreads();

        // projection: this thread computes outputs o = tg + 8*j for its pixel
        unsigned long long acc2[8];
#pragma unroll
        for (int j = 0; j < 8; j++) acc2[j] = pk2(0.f, 0.f);
#pragma unroll
        for (int c4 = 0; c4 < 16; c4++) {
            float4 s4 = *(const float4*)&sm_s[pixL][c4 * 4];
            unsigned long long sxy = pk2(s4.x, s4.y);
            unsigned long long szw = pk2(s4.z, s4.w);
#pragma unroll
            for (int j = 0; j < 8; j++) {
                int o = tg + 8 * j;
                float4 w4 = *(const float4*)&w_s[o][c4 * 4];
                acc2[j] = fma2(pk2(w4.x, w4.y), sxy, acc2[j]);
                acc2[j] = fma2(pk2(w4.z, w4.w), szw, acc2[j]);
            }
        }
#pragma unroll
        for (int j = 0; j < 8; j++) {
            float lo, hi;
            upk2(acc2[j], lo, hi);
            sm_o[tg + 8 * j][pixL] = lo + hi;
        }
        __syncthreads();

        // global write (coalesced)
        if (pr == 1) {
            // queries: pixel-major [N,S,C]
            float* qb = g_Qt + (size_t)pg0 * 64;
#pragma unroll
            for (int j = 0; j < 8; j++) {
                int idx = tid + 256 * j;          // 2048 values
                int p = idx >> 6, c = idx & 63;
                qb[(size_t)p * 64 + c] = sm_o[c][p];
            }
        } else {
            float* dst = (pr == 0) ? g_K : g_V;   // channel-major [N,C,S]
#pragma unroll
            for (int j = 0; j < 8; j++) {
                int idx = tid + 256 * j;
                int r = idx >> 5, p = idx & 31;
                dst[((size_t)(n * 64 + r)) * SS + sIn + p] = sm_o[r][p];
            }
        }
        __syncthreads();
    }
}

// ---------------- K2: per key-row max & sum(exp) over S ----------------
__global__ __launch_bounds__(256) void k2_stats() {
    __shared__ float red[256];
    int r = blockIdx.x;                        // 256 rows
    const float4* row = (const float4*)(g_K + (size_t)r * SS);
    float m = -3.0e38f;
    for (int i = threadIdx.x; i < SS / 4; i += 256) {
        float4 v = row[i];
        m = fmaxf(m, fmaxf(fmaxf(v.x, v.y), fmaxf(v.z, v.w)));
    }
    red[threadIdx.x] = m;
    __syncthreads();
    for (int off = 128; off > 0; off >>= 1) {
        if (threadIdx.x < off) red[threadIdx.x] = fmaxf(red[threadIdx.x], red[threadIdx.x + off]);
        __syncthreads();
    }
    float mx = red[0];
    __syncthreads();
    float sum = 0.f;
    for (int i = threadIdx.x; i < SS / 4; i += 256) {
        float4 v = row[i];
        sum += __expf(v.x - mx) + __expf(v.y - mx) + __expf(v.z - mx) + __expf(v.w - mx);
    }
    red[threadIdx.x] = sum;
    __syncthreads();
    for (int off = 128; off > 0; off >>= 1) {
        if (threadIdx.x < off) red[threadIdx.x] += red[threadIdx.x + off];
        __syncthreads();
    }
    if (threadIdx.x == 0) { g_stats[r * 2] = mx; g_stats[r * 2 + 1] = red[0]; }
}

// ---------------- K3: context partials ctxp[nh][chunk][k,v] ----------------
__global__ __launch_bounds__(256) void k3_ctx() {
    __shared__ float4 Ks[16][17];
    __shared__ float4 Vs[16][17];
    int nh = blockIdx.x;                       // 16
    int n = nh >> 2, h = nh & 3;
    int chunk = blockIdx.y;                    // 64 chunks of 1024 s
    int sBase = chunk * 1024;
    int t = threadIdx.x;
    int lr = t >> 4, lc4 = t & 15;             // load role
    int k = t >> 4, v = t & 15;                // compute role
    size_t rowBase = ((size_t)(n * 64 + h * 16 + lr)) * SS;
    float mx = g_stats[(n * 64 + h * 16 + lr) * 2];
    float acc = 0.f;
    for (int st = 0; st < 16; st++) {
        int s0 = sBase + st * 64;
        float4 kv = *(const float4*)(g_K + rowBase + s0 + lc4 * 4);
        float4 vv = *(const float4*)(g_V + rowBase + s0 + lc4 * 4);
        kv.x = __expf(kv.x - mx); kv.y = __expf(kv.y - mx);
        kv.z = __expf(kv.z - mx); kv.w = __expf(kv.w - mx);
        Ks[lr][lc4] = kv; Vs[lr][lc4] = vv;
        __syncthreads();
#pragma unroll
        for (int s4 = 0; s4 < 16; s4++) {
            float4 a = Ks[k][s4];
            float4 b = Vs[v][s4];
            acc += a.x * b.x + a.y * b.y + a.z * b.z + a.w * b.w;
        }
        __syncthreads();
    }
    g_ctxp[((size_t)nh * 64 + chunk) * 256 + k * 16 + v] = acc;
}

// ---------------- K3r: reduce partials (deterministic, no atomics) ----------------
__global__ __launch_bounds__(256) void k3_reduce() {
    int nh = blockIdx.x;
    int t = threadIdx.x;
    float a = 0.f;
    for (int c = 0; c < 64; c++) a += g_ctxp[((size_t)nh * 64 + c) * 256 + t];
    g_ctx[nh * 256 + t] = a;
}

// ---------------- K3b: B[n][o][kk] = sum_v rp_w[o][h*16+v]*ctx[h][k][v]/Z[kk] ----
__global__ __launch_bounds__(256) void k3b_fold(const float* __restrict__ rpw) {
    int n = blockIdx.x;                        // 4
    for (int idx = threadIdx.x; idx < 4096; idx += 256) {
        int o = idx >> 6, kk = idx & 63;
        int h = kk >> 4, k = kk & 15;
        const float* cx = g_ctx + (n * 4 + h) * 256 + k * 16;
        const float* wr = rpw + o * 64 + h * 16;
        float a = 0.f;
#pragma unroll
        for (int vv = 0; vv < 16; vv++) a += wr[vv] * cx[vv];
        g_B[n * 4096 + idx] = a / g_stats[(n * 64 + kk) * 2 + 1];
    }
}

// ---------------- K4: query softmax + B-GEMM + bias -> out [N,C,H,W] ----------------
__global__ __launch_bounds__(256) void k4_out(const float* __restrict__ rpb,
                                              float* __restrict__ out) {
    __shared__ float B_s[64][68];
    __shared__ float sm_q[32][68];
    __shared__ float sm_o[64][33];
    __shared__ float bias_s[64];

    int tid  = threadIdx.x;
    int pixL = tid >> 3;
    int tg   = tid & 7;
    int c0   = tg * 8;

    long pg0 = (long)blockIdx.x * 32;
    int n    = (int)(pg0 >> 16);
    int sIn  = (int)(pg0 & 65535);

    const float* Bn = g_B + (size_t)n * 4096;
    for (int i = tid; i < 4096; i += 256) B_s[i >> 6][i & 63] = Bn[i];
    if (tid < 64) bias_s[tid] = rpb[tid];

    // load 8 query channels (pixel-major; coalesced)
    const float* qp = g_Qt + ((size_t)pg0 + pixL) * 64 + c0;
    float4 qa = *(const float4*)qp;
    float4 qb = *(const float4*)(qp + 4);
    float q[8] = {qa.x, qa.y, qa.z, qa.w, qb.x, qb.y, qb.z, qb.w};

    // softmax over 16 channels per head: this thread + partner (tg^1)
    float m = q[0];
#pragma unroll
    for (int j = 1; j < 8; j++) m = fmaxf(m, q[j]);
    m = fmaxf(m, __shfl_xor_sync(0xffffffffu, m, 1));
    float e[8], sum = 0.f;
#pragma unroll
    for (int j = 0; j < 8; j++) { e[j] = __expf(q[j] - m); sum += e[j]; }
    sum += __shfl_xor_sync(0xffffffffu, sum, 1);
    float inv = 1.f / sum;
    *(float4*)&sm_q[pixL][c0]     = make_float4(e[0] * inv, e[1] * inv, e[2] * inv, e[3] * inv);
    *(float4*)&sm_q[pixL][c0 + 4] = make_float4(e[4] * inv, e[5] * inv, e[6] * inv, e[7] * inv);
    __syncthreads();

    unsigned long long acc2[8];
#pragma unroll
    for (int j = 0; j < 8; j++) acc2[j] = pk2(0.f, 0.f);
#pragma unroll
    for (int c4 = 0; c4 < 16; c4++) {
        float4 s4 = *(const float4*)&sm_q[pixL][c4 * 4];
        unsigned long long sxy = pk2(s4.x, s4.y);
        unsigned long long szw = pk2(s4.z, s4.w);
#pragma unroll
        for (int j = 0; j < 8; j++) {
            int o = tg + 8 * j;
            float4 w4 = *(const float4*)&B_s[o][c4 * 4];
            acc2[j] = fma2(pk2(w4.x, w4.y), sxy, acc2[j]);
            acc2[j] = fma2(pk2(w4.z, w4.w), szw, acc2[j]);
        }
    }
#pragma unroll
    for (int j = 0; j < 8; j++) {
        float lo, hi;
        upk2(acc2[j], lo, hi);
        int o = tg + 8 * j;
        sm_o[o][pixL] = lo + hi + bias_s[o];
    }
    __syncthreads();

#pragma unroll
    for (int j = 0; j < 8; j++) {
        int idx = tid + 256 * j;
        int r = idx >> 5, p = idx & 31;
        out[((size_t)(n * 64 + r)) * SS + sIn + p] = sm_o[r][p];
    }
}

// ---------------- launch ----------------
extern "C" void kernel_launch(void* const* d_in, const int* in_sizes, int n_in,
                              void* d_out, int out_size) {
    const float* x   = (const float*)d_in[0];
    const float* kow = (const float*)d_in[1];
    const float* kob = (const float*)d_in[2];
    const float* kw  = (const float*)d_in[3];
    const float* qow = (const float*)d_in[4];
    const float* qob = (const float*)d_in[5];
    const float* qw  = (const float*)d_in[6];
    const float* vow = (const float*)d_in[7];
    const float* vob = (const float*)d_in[8];
    const float* vw  = (const float*)d_in[9];
    const float* rpw = (const float*)d_in[10];
    const float* rpb = (const float*)d_in[11];
    float* out = (float*)d_out;

    k0_transpose<<<NS / 64, 256>>>(x);
    k1_kqv<<<NS / 32, 256>>>(kow, kob, kw, qow, qob, qw, vow, vob, vw);
    k2_stats<<<NB * CC, 256>>>();
    k3_ctx<<<dim3(16, 64), 256>>>();
    k3_reduce<<<16, 256>>>();
    k3b_fold<<<NB, 256>>>(rpw);
    k4_out<<<NS / 32, 256>>>(rpb, out);
}

// round 2
// speedup vs baseline: 1.8078x; 1.8078x over previous
#include <cuda_runtime.h>
#include <cstdint>

#define NB 4
#define CC 64
#define SS 65536    // H*W
#define NS 262144   // NB*SS

// ---------------- scratch ----------------
__device__ float g_Yk[(size_t)NS * CC];   // k_w·x, pixel-major [N,S,C]
__device__ float g_Yq[(size_t)NS * CC];
__device__ float g_Yv[(size_t)NS * CC];
__device__ float g_off[(size_t)6 * NS];   // (ky,kx,qy,qx,vy,vx) planes
__device__ float g_ctxp[1024 * 1024];     // per-block ctx partials [blk][h*256+k*16+v]
__device__ float g_zp[1024 * 64];         // per-block Z partials
__device__ float g_ctx[NB * 1024];        // ctx [n][h][k][v]
__device__ float g_Z[NB * 64];            // sum(exp(keys)) per key row
__device__ float g_B[NB * 64 * 64];       // folded (ctx^T ∘ rp_w)/Z   [n][o][kk]

// ---------------- packed f32x2 helpers ----------------
typedef unsigned long long ull;
__device__ __forceinline__ ull pk2(float lo, float hi) {
    ull r; asm("mov.b64 %0, {%1, %2};" : "=l"(r) : "f"(lo), "f"(hi)); return r;
}
__device__ __forceinline__ void upk2(ull v, float& lo, float& hi) {
    asm("mov.b64 {%0, %1}, %2;" : "=f"(lo), "=f"(hi) : "l"(v));
}
__device__ __forceinline__ ull fma2(ull a, ull b, ull c) {
    ull d; asm("fma.rn.f32x2 %0, %1, %2, %3;" : "=l"(d) : "l"(a), "l"(b), "l"(c)); return d;
}

// =============== K_A: offsets + 3 projections (no sampling) ===============
// block = 64 pixels, 256 threads.
__global__ __launch_bounds__(256) void k_a(
    const float* __restrict__ x,
    const float* __restrict__ kow, const float* __restrict__ kob, const float* __restrict__ kw,
    const float* __restrict__ qow, const float* __restrict__ qob, const float* __restrict__ qw,
    const float* __restrict__ vow, const float* __restrict__ vob, const float* __restrict__ vw) {
    __shared__ float xs[64][65];   // [c][p]
    __shared__ float wu[64][66];   // weights transposed [c][o]  (unioned with output [o][p])
    __shared__ float ow_s[6][64];
    __shared__ float ob_s[6];

    int tid = threadIdx.x;
    int pg0 = blockIdx.x * 64;
    int n   = pg0 >> 16;
    int sIn = pg0 & 65535;

    const float* xb = x + (size_t)n * CC * SS + sIn;
    for (int idx = tid; idx < 4096; idx += 256) {
        int c = idx >> 6, p = idx & 63;
        xs[c][p] = xb[(size_t)c * SS + p];
    }
    for (int i = tid; i < 128; i += 256) ow_s[0 + (i >> 6)][i & 63] = kow[i];
    for (int i = tid; i < 128; i += 256) ow_s[2 + (i >> 6)][i & 63] = qow[i];
    for (int i = tid; i < 128; i += 256) ow_s[4 + (i >> 6)][i & 63] = vow[i];
    if (tid < 2) { ob_s[tid] = kob[tid]; ob_s[2 + tid] = qob[tid]; ob_s[4 + tid] = vob[tid]; }
    __syncthreads();

    // ---- offsets: 64 pixels x 4 channel-groups
    {
        int p = tid >> 2, cg = tid & 3;
        float od[6] = {0.f, 0.f, 0.f, 0.f, 0.f, 0.f};
#pragma unroll
        for (int i = 0; i < 16; i++) {
            float xv = xs[cg * 16 + i][p];
#pragma unroll
            for (int d = 0; d < 6; d++) od[d] += xv * ow_s[d][cg * 16 + i];
        }
#pragma unroll
        for (int d = 0; d < 6; d++) {
            od[d] += __shfl_xor_sync(0xffffffffu, od[d], 1);
            od[d] += __shfl_xor_sync(0xffffffffu, od[d], 2);
        }
        if (cg == 0) {
#pragma unroll
            for (int d = 0; d < 6; d++)
                g_off[(size_t)d * NS + pg0 + p] = od[d] + ob_s[d];
        }
    }

    // ---- 3 projections
    const float* wp3[3] = {kw, qw, vw};
    float* yd3[3] = {g_Yk, g_Yq, g_Yv};
    int og = tid >> 5, pl = tid & 31;

    for (int pr = 0; pr < 3; pr++) {
        __syncthreads();
        const float* wp = wp3[pr];
        for (int idx = tid; idx < 4096; idx += 256) {
            int o = idx >> 6, c = idx & 63;
            wu[c][o] = wp[idx];
        }
        __syncthreads();

        ull acc[8];
#pragma unroll
        for (int m = 0; m < 8; m++) acc[m] = pk2(0.f, 0.f);
#pragma unroll 8
        for (int c = 0; c < 64; c++) {
            float xa = xs[c][pl], xc = xs[c][pl + 32];
            ull xda = pk2(xa, xa), xdb = pk2(xc, xc);
#pragma unroll
            for (int m = 0; m < 4; m++) {
                float2 w2 = *(const float2*)&wu[c][og * 8 + 2 * m];
                ull wd = pk2(w2.x, w2.y);
                acc[m]     = fma2(wd, xda, acc[m]);
                acc[4 + m] = fma2(wd, xdb, acc[4 + m]);
            }
        }
        __syncthreads();
#pragma unroll
        for (int m = 0; m < 4; m++) {
            float lo, hi;
            upk2(acc[m], lo, hi);
            wu[og * 8 + 2 * m][pl] = lo; wu[og * 8 + 2 * m + 1][pl] = hi;
            upk2(acc[4 + m], lo, hi);
            wu[og * 8 + 2 * m][pl + 32] = lo; wu[og * 8 + 2 * m + 1][pl + 32] = hi;
        }
        __syncthreads();
        float* yb = yd3[pr] + (size_t)pg0 * 64;
        for (int idx = tid; idx < 4096; idx += 256) {
            int p = idx >> 6, c = idx & 63;
            yb[(size_t)p * 64 + c] = wu[c][p];
        }
    }
}

// =============== K_B: gather K,V + exp + context/Z partials ===============
// block handles 256 pixels (4 tiles of 64); 256 threads.
__global__ __launch_bounds__(256) void k_b() {
    __shared__ float Ke[64][68];
    __shared__ float Vs[64][68];

    int tid = threadIdx.x;
    int h = tid >> 6, k = (tid >> 2) & 15, vg = tid & 3;
    int p4 = tid >> 2, qd = tid & 3;

    float a0 = 0.f, a1 = 0.f, a2 = 0.f, a3 = 0.f, z = 0.f;

    for (int tile = 0; tile < 4; tile++) {
        int pg0 = (blockIdx.x * 4 + tile) * 64;
        int n   = pg0 >> 16;
        int sIn = pg0 & 65535;
        long pG = (long)pg0 + p4;
        int s   = sIn + p4;
        int yI  = s >> 8, xI = s & 255;

#pragma unroll
        for (int tv = 0; tv < 2; tv++) {
            const float* Ysrc = tv ? g_Yv : g_Yk;
            int dB = tv ? 4 : 0;
            float oy = g_off[(size_t)dB * NS + pG];
            float ox = g_off[(size_t)(dB + 1) * NS + pG];
            float py = (float)yI + oy, px = (float)xI + ox;
            float y0f = floorf(py), x0f = floorf(px);
            int iy0 = (int)y0f, ix0 = (int)x0f;
            float ty = py - y0f, tx = px - x0f;
            float wg[4] = {(1.f - ty) * (1.f - tx), (1.f - ty) * tx,
                           ty * (1.f - tx), ty * tx};
            float4 acc[4];
#pragma unroll
            for (int i = 0; i < 4; i++) acc[i] = make_float4(0.f, 0.f, 0.f, 0.f);
#pragma unroll
            for (int t = 0; t < 4; t++) {
                int iy = iy0 + (t >> 1), ix = ix0 + (t & 1);
                if (iy >= 0 && iy < 256 && ix >= 0 && ix < 256) {
                    const float4* tp = (const float4*)(Ysrc +
                        ((((size_t)n << 16) | ((size_t)iy << 8) | (size_t)ix) * 64) + qd * 16);
                    float w = wg[t];
#pragma unroll
                    for (int i = 0; i < 4; i++) {
                        float4 v = tp[i];
                        acc[i].x += w * v.x; acc[i].y += w * v.y;
                        acc[i].z += w * v.z; acc[i].w += w * v.w;
                    }
                }
            }
            if (tv == 0) {
#pragma unroll
                for (int i = 0; i < 4; i++) {
                    acc[i].x = __expf(acc[i].x); acc[i].y = __expf(acc[i].y);
                    acc[i].z = __expf(acc[i].z); acc[i].w = __expf(acc[i].w);
                    *(float4*)&Ke[p4][qd * 16 + 4 * i] = acc[i];
                }
            } else {
#pragma unroll
                for (int i = 0; i < 4; i++)
                    *(float4*)&Vs[p4][qd * 16 + 4 * i] = acc[i];
            }
        }
        __syncthreads();

#pragma unroll 8
        for (int p = 0; p < 64; p++) {
            float kv = Ke[p][h * 16 + k];
            float4 v4 = *(const float4*)&Vs[p][h * 16 + vg * 4];
            a0 += kv * v4.x; a1 += kv * v4.y; a2 += kv * v4.z; a3 += kv * v4.w;
            z += kv;
        }
        __syncthreads();
    }

    size_t base = (size_t)blockIdx.x * 1024 + h * 256 + k * 16 + vg * 4;
    g_ctxp[base + 0] = a0; g_ctxp[base + 1] = a1;
    g_ctxp[base + 2] = a2; g_ctxp[base + 3] = a3;
    if (vg == 0) g_zp[blockIdx.x * 64 + h * 16 + k] = z;
}

// =============== reduce partials (deterministic) ===============
__global__ __launch_bounds__(256) void k_red() {
    int n = blockIdx.x, t = threadIdx.x;
#pragma unroll
    for (int j = 0; j < 4; j++) {
        int idx = j * 256 + t;
        float s = 0.f;
        for (int b = 0; b < 256; b++)
            s += g_ctxp[((size_t)(n * 256 + b)) * 1024 + idx];
        g_ctx[n * 1024 + idx] = s;
    }
    if (t < 64) {
        float s = 0.f;
        for (int b = 0; b < 256; b++)
            s += g_zp[(n * 256 + b) * 64 + t];
        g_Z[n * 64 + t] = s;
    }
}

// =============== fold: B[n][o][kk] ===============
__global__ __launch_bounds__(256) void k_fold(const float* __restrict__ rpw) {
    int n = blockIdx.x;
    for (int idx = threadIdx.x; idx < 4096; idx += 256) {
        int o = idx >> 6, kk = idx & 63;
        int h = kk >> 4, k = kk & 15;
        const float* cx = g_ctx + n * 1024 + h * 256 + k * 16;
        const float* wr = rpw + o * 64 + h * 16;
        float a = 0.f;
#pragma unroll
        for (int v = 0; v < 16; v++) a += wr[v] * cx[v];
        g_B[n * 4096 + idx] = a / g_Z[n * 64 + kk];
    }
}

// =============== K_C: gather Q + channel softmax + B-GEMM + bias ===============
__global__ __launch_bounds__(256) void k_c(const float* __restrict__ rpb,
                                           float* __restrict__ out) {
    __shared__ float qs[64][65];   // [kk][p]
    __shared__ float bu[64][66];   // B transposed [kk][o] (unioned with output [o][p])
    __shared__ float bias_s[64];

    int tid = threadIdx.x;
    int pg0 = blockIdx.x * 64;
    int n   = pg0 >> 16;
    int sIn = pg0 & 65535;

    const float* Bn = g_B + (size_t)n * 4096;
    for (int idx = tid; idx < 4096; idx += 256) {
        int o = idx >> 6, kk = idx & 63;
        bu[kk][o] = Bn[idx];
    }
    if (tid < 64) bias_s[tid] = rpb[tid];

    // ---- gather q (bilinear of Y_q)
    {
        int p4 = tid >> 2, qd = tid & 3;
        long pG = (long)pg0 + p4;
        int s = sIn + p4;
        int yI = s >> 8, xI = s & 255;
        float oy = g_off[(size_t)2 * NS + pG];
        float ox = g_off[(size_t)3 * NS + pG];
        float py = (float)yI + oy, px = (float)xI + ox;
        float y0f = floorf(py), x0f = floorf(px);
        int iy0 = (int)y0f, ix0 = (int)x0f;
        float ty = py - y0f, tx = px - x0f;
        float wg[4] = {(1.f - ty) * (1.f - tx), (1.f - ty) * tx,
                       ty * (1.f - tx), ty * tx};
        float acc[16];
#pragma unroll
        for (int i = 0; i < 16; i++) acc[i] = 0.f;
#pragma unroll
        for (int t = 0; t < 4; t++) {
            int iy = iy0 + (t >> 1), ix = ix0 + (t & 1);
            if (iy >= 0 && iy < 256 && ix >= 0 && ix < 256) {
                const float4* tp = (const float4*)(g_Yq +
                    ((((size_t)n << 16) | ((size_t)iy << 8) | (size_t)ix) * 64) + qd * 16);
                float w = wg[t];
#pragma unroll
                for (int i = 0; i < 4; i++) {
                    float4 v = tp[i];
                    acc[4 * i + 0] += w * v.x; acc[4 * i + 1] += w * v.y;
                    acc[4 * i + 2] += w * v.z; acc[4 * i + 3] += w * v.w;
                }
            }
        }
#pragma unroll
        for (int i = 0; i < 16; i++) qs[qd * 16 + i][p4] = acc[i];
    }
    __syncthreads();

    // ---- channel softmax per head (16 channels)
    {
        int p = tid >> 2, hp = tid & 3;
        float v[16];
#pragma unroll
        for (int i = 0; i < 16; i++) v[i] = qs[hp * 16 + i][p];
        float m = v[0];
#pragma unroll
        for (int i = 1; i < 16; i++) m = fmaxf(m, v[i]);
        float sum = 0.f;
#pragma unroll
        for (int i = 0; i < 16; i++) { v[i] = __expf(v[i] - m); sum += v[i]; }
        float inv = 1.f / sum;
#pragma unroll
        for (int i = 0; i < 16; i++) qs[hp * 16 + i][p] = v[i] * inv;
    }
    __syncthreads();

    // ---- GEMM out = B · q_sm
    int og = tid >> 5, pl = tid & 31;
    ull acc[8];
#pragma unroll
    for (int m = 0; m < 8; m++) acc[m] = pk2(0.f, 0.f);
#pragma unroll 8
    for (int c = 0; c < 64; c++) {
        float xa = qs[c][pl], xc = qs[c][pl + 32];
        ull xda = pk2(xa, xa), xdb = pk2(xc, xc);
#pragma unroll
        for (int m = 0; m < 4; m++) {
            float2 w2 = *(const float2*)&bu[c][og * 8 + 2 * m];
            ull wd = pk2(w2.x, w2.y);
            acc[m]     = fma2(wd, xda, acc[m]);
            acc[4 + m] = fma2(wd, xdb, acc[4 + m]);
        }
    }
    __syncthreads();
#pragma unroll
    for (int m = 0; m < 4; m++) {
        int o0 = og * 8 + 2 * m;
        float lo, hi;
        upk2(acc[m], lo, hi);
        bu[o0][pl] = lo + bias_s[o0]; bu[o0 + 1][pl] = hi + bias_s[o0 + 1];
        upk2(acc[4 + m], lo, hi);
        bu[o0][pl + 32] = lo + bias_s[o0]; bu[o0 + 1][pl + 32] = hi + bias_s[o0 + 1];
    }
    __syncthreads();

    for (int idx = tid; idx < 4096; idx += 256) {
        int c = idx >> 6, p = idx & 63;
        out[((size_t)(n * 64 + c)) * SS + sIn + p] = bu[c][p];
    }
}

// ---------------- launch ----------------
extern "C" void kernel_launch(void* const* d_in, const int* in_sizes, int n_in,
                              void* d_out, int out_size) {
    const float* x   = (const float*)d_in[0];
    const float* kow = (const float*)d_in[1];
    const float* kob = (const float*)d_in[2];
    const float* kw  = (const float*)d_in[3];
    const float* qow = (const float*)d_in[4];
    const float* qob = (const float*)d_in[5];
    const float* qw  = (const float*)d_in[6];
    const float* vow = (const float*)d_in[7];
    const float* vob = (const float*)d_in[8];
    const float* vw  = (const float*)d_in[9];
    const float* rpw = (const float*)d_in[10];
    const float* rpb = (const float*)d_in[11];
    float* out = (float*)d_out;

    k_a<<<NS / 64, 256>>>(x, kow, kob, kw, qow, qob, qw, vow, vob, vw);
    k_b<<<1024, 256>>>();
    k_red<<<NB, 256>>>();
    k_fold<<<NB, 256>>>(rpw);
    k_c<<<NS / 64, 256>>>(rpb, out);
}

// round 4
// speedup vs baseline: 1.9284x; 1.0667x over previous
#include <cuda_runtime.h>
#include <cstdint>

#define NB 4
#define CC 64
#define SS 65536    // H*W
#define NS 262144   // NB*SS

// ---------------- scratch ----------------
__device__ float g_Yk[(size_t)NS * CC];   // pixel-major [N,S,C]
__device__ float g_Yq[(size_t)NS * CC];
__device__ float g_Yv[(size_t)NS * CC];
__device__ float g_off[(size_t)6 * NS];   // (ky,kx,qy,qx,vy,vx)
__device__ float g_ctxp[256 * 1024];      // per-block ctx partials
__device__ float g_zp[256 * 64];          // per-block Z partials
__device__ float g_ctx[NB * 1024];        // ctx [n][h][k][v]
__device__ float g_Z[NB * 64];
__device__ float g_B[NB * 64 * 64];       // folded matrix [n][o][kk]

// ---------------- packed f32x2 helpers ----------------
typedef unsigned long long ull;
__device__ __forceinline__ ull pk2(float lo, float hi) {
    ull r; asm("mov.b64 %0, {%1, %2};" : "=l"(r) : "f"(lo), "f"(hi)); return r;
}
__device__ __forceinline__ void upk2(ull v, float& lo, float& hi) {
    asm("mov.b64 {%0, %1}, %2;" : "=f"(lo), "=f"(hi) : "l"(v));
}
__device__ __forceinline__ ull fma2(ull a, ull b, ull c) {
    ull d; asm("fma.rn.f32x2 %0, %1, %2, %3;" : "=l"(d) : "l"(a), "l"(b), "l"(c)); return d;
}

// =============== K_A: offsets + 3 projections, dense fma2 GEMM ===============
// 128 threads, 64-pixel tile. Each thread: 8 outputs x 4 pixels.
__global__ __launch_bounds__(128) void k_a(
    const float* __restrict__ x,
    const float* __restrict__ kow, const float* __restrict__ kob, const float* __restrict__ kw,
    const float* __restrict__ qow, const float* __restrict__ qob, const float* __restrict__ qw,
    const float* __restrict__ vow, const float* __restrict__ vob, const float* __restrict__ vw) {
    __shared__ float xs[64][68];   // [c][p]
    __shared__ float ws[64][68];   // [c][o]
    __shared__ float ow_s[6][64];
    __shared__ float ob_s[6];

    int tid = threadIdx.x;
    int pg0 = blockIdx.x * 64;
    int n   = pg0 >> 16;
    int sIn = pg0 & 65535;

    const float* xb = x + (size_t)n * CC * SS + sIn;
#pragma unroll
    for (int it = 0; it < 32; it++) {
        int idx = tid + 128 * it;
        int c = idx >> 6, p = idx & 63;
        xs[c][p] = xb[(size_t)c * SS + p];
    }
    if (tid < 128) {
        ow_s[0 + (tid >> 6)][tid & 63] = kow[tid];
    }
    { int i = tid; if (i < 128) ow_s[2 + (i >> 6)][i & 63] = qow[i]; }
    { int i = tid; if (i < 128) ow_s[4 + (i >> 6)][i & 63] = vow[i]; }
    if (tid < 2) { ob_s[tid] = kob[tid]; ob_s[2 + tid] = qob[tid]; ob_s[4 + tid] = vob[tid]; }
    __syncthreads();

    // ---- offsets: 64 pixels x 2 halves
    {
        int p = tid >> 1, half = tid & 1;
        float od[6] = {0.f, 0.f, 0.f, 0.f, 0.f, 0.f};
#pragma unroll
        for (int i = 0; i < 32; i++) {
            int c = half * 32 + i;
            float xv = xs[c][p];
#pragma unroll
            for (int d = 0; d < 6; d++) od[d] += xv * ow_s[d][c];
        }
#pragma unroll
        for (int d = 0; d < 6; d++) od[d] += __shfl_xor_sync(0xffffffffu, od[d], 1);
        if (half == 0) {
#pragma unroll
            for (int d = 0; d < 6; d++)
                g_off[(size_t)d * NS + pg0 + p] = od[d] + ob_s[d];
        }
    }

    const float* wp3[3] = {kw, qw, vw};
    float* yd3[3] = {g_Yk, g_Yq, g_Yv};
    int og = tid >> 4;   // 0..7  -> outputs og*8..og*8+7
    int pg = tid & 15;   // 0..15 -> pixels pg*4..pg*4+3

    for (int pr = 0; pr < 3; pr++) {
        __syncthreads();
        const float* wp = wp3[pr];
#pragma unroll
        for (int it = 0; it < 32; it++) {
            int idx = tid + 128 * it;
            int o = idx >> 6, c = idx & 63;
            ws[c][o] = wp[idx];
        }
        __syncthreads();

        ull acc[4][4];   // [output-pair j][pixel i]
#pragma unroll
        for (int j = 0; j < 4; j++)
#pragma unroll
            for (int i = 0; i < 4; i++) acc[j][i] = pk2(0.f, 0.f);

#pragma unroll 4
        for (int c = 0; c < 64; c++) {
            float2 x01 = *(const float2*)&xs[c][pg * 4];
            float2 x23 = *(const float2*)&xs[c][pg * 4 + 2];
            ull xd[4] = {pk2(x01.x, x01.x), pk2(x01.y, x01.y),
                         pk2(x23.x, x23.x), pk2(x23.y, x23.y)};
            float4 wa = *(const float4*)&ws[c][og * 8];
            float4 wb = *(const float4*)&ws[c][og * 8 + 4];
            ull wd[4] = {pk2(wa.x, wa.y), pk2(wa.z, wa.w),
                         pk2(wb.x, wb.y), pk2(wb.z, wb.w)};
#pragma unroll
            for (int j = 0; j < 4; j++)
#pragma unroll
                for (int i = 0; i < 4; i++)
                    acc[j][i] = fma2(wd[j], xd[i], acc[j][i]);
        }

        // epilogue: pixel-major [p][c]; per pixel 8 consecutive outputs = 2 float4
        float* yb = yd3[pr] + (size_t)pg0 * 64;
#pragma unroll
        for (int i = 0; i < 4; i++) {
            int p = pg * 4 + i;
            float a0, a1, a2, a3, a4, a5, a6, a7;
            upk2(acc[0][i], a0, a1); upk2(acc[1][i], a2, a3);
            upk2(acc[2][i], a4, a5); upk2(acc[3][i], a6, a7);
            float* dst = yb + (size_t)p * 64 + og * 8;
            *(float4*)dst       = make_float4(a0, a1, a2, a3);
            *(float4*)(dst + 4) = make_float4(a4, a5, a6, a7);
        }
    }
}

// =============== K_B: gather K,V + exp + context/Z partials ===============
__global__ __launch_bounds__(256) void k_b() {
    __shared__ float Ke[64][68];
    __shared__ float Vs[64][68];

    int tid = threadIdx.x;
    int h = tid >> 6, k = (tid >> 2) & 15, vg = tid & 3;
    int p4 = tid >> 2, qd = tid & 3;

    float a0 = 0.f, a1 = 0.f, a2 = 0.f, a3 = 0.f, z = 0.f;

    for (int tile = 0; tile < 16; tile++) {
        int pg0 = (blockIdx.x * 16 + tile) * 64;
        int n   = pg0 >> 16;
        int sIn = pg0 & 65535;
        long pG = (long)pg0 + p4;
        int s   = sIn + p4;
        int yI  = s >> 8, xI = s & 255;

#pragma unroll
        for (int tv = 0; tv < 2; tv++) {
            const float* Ysrc = tv ? g_Yv : g_Yk;
            int dB = tv ? 4 : 0;
            float oy = g_off[(size_t)dB * NS + pG];
            float ox = g_off[(size_t)(dB + 1) * NS + pG];
            float py = (float)yI + oy, px = (float)xI + ox;
            float y0f = floorf(py), x0f = floorf(px);
            int iy0 = (int)y0f, ix0 = (int)x0f;
            float ty = py - y0f, tx = px - x0f;
            float wg[4] = {(1.f - ty) * (1.f - tx), (1.f - ty) * tx,
                           ty * (1.f - tx), ty * tx};
            float4 acc[4];
#pragma unroll
            for (int i = 0; i < 4; i++) acc[i] = make_float4(0.f, 0.f, 0.f, 0.f);
#pragma unroll
            for (int t = 0; t < 4; t++) {
                int iy = iy0 + (t >> 1), ix = ix0 + (t & 1);
                if (iy >= 0 && iy < 256 && ix >= 0 && ix < 256) {
                    const float4* tp = (const float4*)(Ysrc +
                        ((((size_t)n << 16) | ((size_t)iy << 8) | (size_t)ix) * 64) + qd * 16);
                    float w = wg[t];
#pragma unroll
                    for (int i = 0; i < 4; i++) {
                        float4 v = tp[i];
                        acc[i].x += w * v.x; acc[i].y += w * v.y;
                        acc[i].z += w * v.z; acc[i].w += w * v.w;
                    }
                }
            }
            if (tv == 0) {
#pragma unroll
                for (int i = 0; i < 4; i++) {
                    acc[i].x = __expf(acc[i].x); acc[i].y = __expf(acc[i].y);
                    acc[i].z = __expf(acc[i].z); acc[i].w = __expf(acc[i].w);
                    *(float4*)&Ke[p4][qd * 16 + 4 * i] = acc[i];
                }
            } else {
#pragma unroll
                for (int i = 0; i < 4; i++)
                    *(float4*)&Vs[p4][qd * 16 + 4 * i] = acc[i];
            }
        }
        __syncthreads();

#pragma unroll 8
        for (int p = 0; p < 64; p++) {
            float kv = Ke[p][h * 16 + k];
            float4 v4 = *(const float4*)&Vs[p][h * 16 + vg * 4];
            a0 += kv * v4.x; a1 += kv * v4.y; a2 += kv * v4.z; a3 += kv * v4.w;
            z += kv;
        }
        __syncthreads();
    }

    size_t base = (size_t)blockIdx.x * 1024 + h * 256 + k * 16 + vg * 4;
    g_ctxp[base + 0] = a0; g_ctxp[base + 1] = a1;
    g_ctxp[base + 2] = a2; g_ctxp[base + 3] = a3;
    if (vg == 0) g_zp[blockIdx.x * 64 + h * 16 + k] = z;
}

// =============== reduce partials: warp per row ===============
__global__ __launch_bounds__(256) void k_red2() {
    int wid = threadIdx.x >> 5, lid = threadIdx.x & 31;
    int row = blockIdx.x * 8 + wid;
    if (blockIdx.x < 512) {
        int n = row >> 10, idx = row & 1023;
        float v = g_ctxp[((size_t)(n * 64 + lid)) * 1024 + idx]
                + g_ctxp[((size_t)(n * 64 + 32 + lid)) * 1024 + idx];
#pragma unroll
        for (int o = 16; o > 0; o >>= 1) v += __shfl_xor_sync(0xffffffffu, v, o);
        if (lid == 0) g_ctx[row] = v;
    } else {
        int zrow = (blockIdx.x - 512) * 8 + wid;
        int n = zrow >> 6, kk = zrow & 63;
        float v = g_zp[(n * 64 + lid) * 64 + kk]
                + g_zp[(n * 64 + 32 + lid) * 64 + kk];
#pragma unroll
        for (int o = 16; o > 0; o >>= 1) v += __shfl_xor_sync(0xffffffffu, v, o);
        if (lid == 0) g_Z[zrow] = v;
    }
}

// =============== fold: B[n][o][kk] ===============
__global__ __launch_bounds__(256) void k_fold2(const float* __restrict__ rpw) {
    int idx = blockIdx.x * 256 + threadIdx.x;    // 16384 outputs
    int n = idx >> 12, o = (idx >> 6) & 63, kk = idx & 63;
    int h = kk >> 4, k = kk & 15;
    const float* cx = g_ctx + n * 1024 + h * 256 + k * 16;
    const float* wr = rpw + o * 64 + h * 16;
    float a = 0.f;
#pragma unroll
    for (int v = 0; v < 16; v++) a += wr[v] * cx[v];
    g_B[n * 4096 + (o << 6) + kk] = a / g_Z[n * 64 + kk];
}

// =============== K_C: gather Q + channel softmax + B-GEMM + bias ===============
// 128 threads, 64-pixel tile. Each thread: 8 output channels x 4 pixels.
__global__ __launch_bounds__(128) void k_c(const float* __restrict__ rpb,
                                           float* __restrict__ out) {
    __shared__ float qs[64][68];   // [kk][p]
    __shared__ float bu[64][68];   // B transposed [kk][o]
    __shared__ float bias_s[64];

    int tid = threadIdx.x;
    int pg0 = blockIdx.x * 64;
    int n   = pg0 >> 16;
    int sIn = pg0 & 65535;

    const float* Bn = g_B + (size_t)n * 4096;
#pragma unroll
    for (int it = 0; it < 32; it++) {
        int idx = tid + 128 * it;
        int o = idx >> 6, kk = idx & 63;
        bu[kk][o] = Bn[idx];
    }
    if (tid < 64) bias_s[tid] = rpb[tid];

    // ---- gather q (bilinear of Y_q): 64 px x 2 halves of 32 channels
    {
        int p2 = tid >> 1, qh = tid & 1;
        long pG = (long)pg0 + p2;
        int s = sIn + p2;
        int yI = s >> 8, xI = s & 255;
        float oy = g_off[(size_t)2 * NS + pG];
        float ox = g_off[(size_t)3 * NS + pG];
        float py = (float)yI + oy, px = (float)xI + ox;
        float y0f = floorf(py), x0f = floorf(px);
        int iy0 = (int)y0f, ix0 = (int)x0f;
        float ty = py - y0f, tx = px - x0f;
        float wg[4] = {(1.f - ty) * (1.f - tx), (1.f - ty) * tx,
                       ty * (1.f - tx), ty * tx};
        float acc[32];
#pragma unroll
        for (int i = 0; i < 32; i++) acc[i] = 0.f;
#pragma unroll
        for (int t = 0; t < 4; t++) {
            int iy = iy0 + (t >> 1), ix = ix0 + (t & 1);
            if (iy >= 0 && iy < 256 && ix >= 0 && ix < 256) {
                const float4* tp = (const float4*)(g_Yq +
                    ((((size_t)n << 16) | ((size_t)iy << 8) | (size_t)ix) * 64) + qh * 32);
                float w = wg[t];
#pragma unroll
                for (int i = 0; i < 8; i++) {
                    float4 v = tp[i];
                    acc[4 * i + 0] += w * v.x; acc[4 * i + 1] += w * v.y;
                    acc[4 * i + 2] += w * v.z; acc[4 * i + 3] += w * v.w;
                }
            }
        }
#pragma unroll
        for (int i = 0; i < 32; i++) qs[qh * 32 + i][p2] = acc[i];
    }
    __syncthreads();

    // ---- channel softmax per head: each thread handles 2 heads of one pixel
    {
        int p = tid >> 1, hb = (tid & 1) * 2;
#pragma unroll
        for (int hh = 0; hh < 2; hh++) {
            int h0 = hb + hh;
            float v[16];
#pragma unroll
            for (int i = 0; i < 16; i++) v[i] = qs[h0 * 16 + i][p];
            float m = v[0];
#pragma unroll
            for (int i = 1; i < 16; i++) m = fmaxf(m, v[i]);
            float sum = 0.f;
#pragma unroll
            for (int i = 0; i < 16; i++) { v[i] = __expf(v[i] - m); sum += v[i]; }
            float inv = 1.f / sum;
#pragma unroll
            for (int i = 0; i < 16; i++) qs[h0 * 16 + i][p] = v[i] * inv;
        }
    }
    __syncthreads();

    // ---- GEMM out = B · q_sm : 8 outputs x 4 pixels per thread
    int og = tid >> 4;   // 0..7
    int pg = tid & 15;   // 0..15
    ull acc[4][4];
#pragma unroll
    for (int j = 0; j < 4; j++)
#pragma unroll
        for (int i = 0; i < 4; i++) acc[j][i] = pk2(0.f, 0.f);

#pragma unroll 4
    for (int c = 0; c < 64; c++) {
        float2 x01 = *(const float2*)&qs[c][pg * 4];
        float2 x23 = *(const float2*)&qs[c][pg * 4 + 2];
        ull xd[4] = {pk2(x01.x, x01.x), pk2(x01.y, x01.y),
                     pk2(x23.x, x23.x), pk2(x23.y, x23.y)};
        float4 wa = *(const float4*)&bu[c][og * 8];
        float4 wb = *(const float4*)&bu[c][og * 8 + 4];
        ull wd[4] = {pk2(wa.x, wa.y), pk2(wa.z, wa.w),
                     pk2(wb.x, wb.y), pk2(wb.z, wb.w)};
#pragma unroll
        for (int j = 0; j < 4; j++)
#pragma unroll
            for (int i = 0; i < 4; i++)
                acc[j][i] = fma2(wd[j], xd[i], acc[j][i]);
    }

    // epilogue: channel-major out[N,C,H,W]; per output-channel a float4 over 4 pixels
#pragma unroll
    for (int j = 0; j < 4; j++) {
        int c0 = og * 8 + 2 * j;
        float l0, h0, l1, h1, l2, h2, l3, h3;
        upk2(acc[j][0], l0, h0); upk2(acc[j][1], l1, h1);
        upk2(acc[j][2], l2, h2); upk2(acc[j][3], l3, h3);
        float b0 = bias_s[c0], b1 = bias_s[c0 + 1];
        float* d0 = out + ((size_t)(n * 64 + c0)) * SS + sIn + pg * 4;
        float* d1 = out + ((size_t)(n * 64 + c0 + 1)) * SS + sIn + pg * 4;
        *(float4*)d0 = make_float4(l0 + b0, l1 + b0, l2 + b0, l3 + b0);
        *(float4*)d1 = make_float4(h0 + b1, h1 + b1, h2 + b1, h3 + b1);
    }
}

// ---------------- launch ----------------
extern "C" void kernel_launch(void* const* d_in, const int* in_sizes, int n_in,
                              void* d_out, int out_size) {
    const float* x   = (const float*)d_in[0];
    const float* kow = (const float*)d_in[1];
    const float* kob = (const float*)d_in[2];
    const float* kw  = (const float*)d_in[3];
    const float* qow = (const float*)d_in[4];
    const float* qob = (const float*)d_in[5];
    const float* qw  = (const float*)d_in[6];
    const float* vow = (const float*)d_in[7];
    const float* vob = (const float*)d_in[8];
    const float* vw  = (const float*)d_in[9];
    const float* rpw = (const float*)d_in[10];
    const float* rpb = (const float*)d_in[11];
    float* out = (float*)d_out;

    k_a<<<NS / 64, 128>>>(x, kow, kob, kw, qow, qob, qw, vow, vob, vw);
    k_b<<<256, 256>>>();
    k_red2<<<544, 256>>>();
    k_fold2<<<64, 256>>>(rpw);
    k_c<<<NS / 64, 128>>>(rpb, out);
}